// round 13
// baseline (speedup 1.0000x reference)
#include <cuda_runtime.h>
#include <cuda_fp16.h>
#include <cstddef>

// ---------------------------------------------------------------------------
// Compile-time Gaussian weights
// ---------------------------------------------------------------------------
constexpr double cexp_pos(double x) {
    double term = 1.0, sum = 1.0;
    for (int i = 1; i < 200; ++i) {
        term *= x / (double)i;
        if (term < 1e-250) break;
        sum += term;
    }
    return sum;
}

template <int KS>
struct Wt { float w[KS]; };

template <int KS>
constexpr Wt<KS> make_w(double sigma) {
    Wt<KS> W{};
    double wd[KS]{};
    double s = 0.0;
    for (int i = 0; i < KS; ++i) {
        double d = (double)(i - KS / 2);
        double e = 1.0 / cexp_pos(d * d / (2.0 * sigma * sigma));
        wd[i] = e;
        s += e;
    }
    for (int i = 0; i < KS; ++i) W.w[i] = (float)(wd[i] / s);
    return W;
}

constexpr Wt<7>   CW0 = make_w<7>(0.6);
constexpr Wt<9>   CW1 = make_w<9>(1.2);
constexpr Wt<17>  CW2 = make_w<17>(2.4);
constexpr Wt<31>  CW3 = make_w<31>(4.8);
constexpr Wt<59>  CW4 = make_w<59>(9.6);
constexpr Wt<117> CW5 = make_w<117>(19.2);

constexpr int H = 512, W = 512;
constexpr int HW = H * W;
constexpr int NROWS = 8 * 3 * H;        // 12288
constexpr int NPIX = NROWS * W;         // 6291456
constexpr int PMAX = 58;

// fp16 h-blurred planes (75.5 MB)
__device__ __align__(16) __half g_scratch[6 * (size_t)NPIX];

// ---------------------------------------------------------------------------
// packed f32x2 helpers (sm_103a FFMA2 path)
// ---------------------------------------------------------------------------
typedef unsigned long long u64;

__device__ __forceinline__ u64 pack2(float lo, float hi) {
    u64 r;
    asm("mov.b64 %0, {%1, %2};" : "=l"(r) : "f"(lo), "f"(hi));
    return r;
}
__device__ __forceinline__ void fma2(u64& acc, u64 a, u64 b) {
    asm("fma.rn.f32x2 %0, %1, %2, %0;" : "+l"(acc) : "l"(a), "l"(b));
}
// d = a*b + c
__device__ __forceinline__ u64 fma2v(u64 a, u64 b, u64 c) {
    u64 d;
    asm("fma.rn.f32x2 %0, %1, %2, %3;" : "=l"(d) : "l"(a), "l"(b), "l"(c));
    return d;
}
__device__ __forceinline__ void unpack2(u64 p, float& lo, float& hi) {
    asm("mov.b64 {%0, %1}, %2;" : "=f"(lo), "=f"(hi) : "l"(p));
}
__device__ __forceinline__ u64 h2f2(unsigned h2) {
    __half2 h = *reinterpret_cast<__half2*>(&h2);
    float2 f = __half22float2(h);
    return pack2(f.x, f.y);
}

// ---------------------------------------------------------------------------
// cp.async helpers
// ---------------------------------------------------------------------------
__device__ __forceinline__ void cp_async16(unsigned daddr, const void* gsrc) {
    asm volatile("cp.async.cg.shared.global [%0], [%1], 16;\n"
                 :: "r"(daddr), "l"(gsrc) : "memory");
}
__device__ __forceinline__ void cp_commit() {
    asm volatile("cp.async.commit_group;\n" ::: "memory");
}
template <int N>
__device__ __forceinline__ void cp_wait() {
    asm volatile("cp.async.wait_group %0;\n" :: "n"(N) : "memory");
}

// ---------------------------------------------------------------------------
// Kernel A: horizontal pass, row-PAIR packed f32x2.
// CTA = 256 thr = 4 row-pairs (8 rows) x 64 lanes; each thread 2 rows x 8 cols.
// smem: float2 per pair, padded every 8 float2 (stride 9): per-16-lane phase
// addresses are all distinct 8B slots -> conflict-free LDS.64.
// ---------------------------------------------------------------------------
constexpr int SR2W = 712;   // float2 entries per pair row (628 valid + pad)

template <int KS>
__device__ __forceinline__ void hconv2(const Wt<KS> Wc,
                                       const float2* __restrict__ s2,
                                       int lane, __half* __restrict__ dstA) {
    constexpr int P  = KS / 2;
    constexpr int S0 = PMAX - P;
    constexpr int Q  = S0 >> 3;
    constexpr int R  = S0 & 7;
    const int base = 9 * (lane + Q);

    u64 win[8], acc[8];
#pragma unroll
    for (int i = 0; i < 7; ++i) {
        float2 v = s2[base + (R + i) + ((R + i) >> 3)];
        win[i] = pack2(v.x, v.y);
    }
#pragma unroll
    for (int t = 0; t < 8; ++t) acc[t] = 0ull;
#pragma unroll
    for (int k = 0; k < KS; ++k) {
        const int j = k + 7;
        {
            float2 v = s2[base + (R + j) + ((R + j) >> 3)];
            win[j & 7] = pack2(v.x, v.y);
        }
        const u64 w2 = pack2(Wc.w[k], Wc.w[k]);
#pragma unroll
        for (int t = 0; t < 8; ++t)
            fma2(acc[t], win[(k + t) & 7], w2);
    }
    // unpack rows, convert to fp16, store 16B per row
    float la[8], lb[8];
#pragma unroll
    for (int t = 0; t < 8; ++t) unpack2(acc[t], la[t], lb[t]);
    __half2 ha[4], hb[4];
#pragma unroll
    for (int q = 0; q < 4; ++q) {
        ha[q] = __floats2half2_rn(la[2 * q], la[2 * q + 1]);
        hb[q] = __floats2half2_rn(lb[2 * q], lb[2 * q + 1]);
    }
    *reinterpret_cast<float4*>(dstA + lane * 8) =
        *reinterpret_cast<const float4*>(ha);
    *reinterpret_cast<float4*>(dstA + W + lane * 8) =
        *reinterpret_cast<const float4*>(hb);
}

__global__ __launch_bounds__(256) void hpass_kernel(const float* __restrict__ img) {
    __shared__ float2 s2[4][SR2W];
    const int pair = threadIdx.x >> 6;     // 0..3
    const int lt   = threadIdx.x & 63;
    const int rowA = blockIdx.x * 8 + pair * 2;

    const float* rpA = img + (size_t)rowA * W;
    const float* rpB = rpA + W;            // same image (rows pair-aligned)
    for (int x = lt; x < W + 2 * PMAX; x += 64) {
        int gx = x - PMAX;
        gx = gx < 0 ? -gx : (gx > W - 1 ? 2 * W - 2 - gx : gx);
        s2[pair][x + (x >> 3)] = make_float2(rpA[gx], rpB[gx]);
    }
    __syncthreads();

    const float2* s = s2[pair];
    __half* base = g_scratch + (size_t)rowA * W;
    hconv2<7>(CW0, s, lt, base + 0 * (size_t)NPIX);
    hconv2<9>(CW1, s, lt, base + 1 * (size_t)NPIX);
    hconv2<17>(CW2, s, lt, base + 2 * (size_t)NPIX);
    hconv2<31>(CW3, s, lt, base + 3 * (size_t)NPIX);
    hconv2<59>(CW4, s, lt, base + 4 * (size_t)NPIX);
    hconv2<117>(CW5, s, lt, base + 5 * (size_t)NPIX);
}

// ---------------------------------------------------------------------------
// Kernel B: vertical pass + DoG, column-PAIR packed f32x2, double-buffered,
// DESCENDING sigma order. Tile = 64 cols x 64 rows; thread = 2 cols x 8 rows.
// fp16 smem tiles: rows of 64 halves (128 B). Slot A 180 rows, slot B 122.
// smem = 302 * 128 B = 38656 B.
// ---------------------------------------------------------------------------
constexpr int VSMEM_BYTES = 302 * 64 * 2;    // 38656
constexpr int BUFA = 0;                       // half-index
constexpr int BUFB = 180 * 64;

template <int KS, int OFF>
__device__ __forceinline__ void load_tile_async(unsigned smb,
                                                const __half* __restrict__ src,
                                                int R0, int tid) {
    constexpr int P  = KS / 2;
    constexpr int NR = 64 + KS - 1;
    const unsigned base = smb + (unsigned)OFF * 2u;
    const int c8 = (tid & 7) * 8;            // half offset of this thread's 16B
#pragma unroll 2
    for (int m = tid >> 3; m < NR; m += 32) {
        int gr = R0 - P + m;
        gr = gr < 0 ? -gr : (gr > H - 1 ? 2 * H - 2 - gr : gr);
        cp_async16(base + (unsigned)(m * 64 + c8) * 2u,
                   src + (size_t)gr * W + c8);
    }
    cp_commit();
}

template <int KS>
__device__ __forceinline__ void vconv2(const Wt<KS> Wc,
                                       const __half* __restrict__ tile,
                                       int g, int lane, u64 acc[8]) {
    // half2 view: row stride = 32 half2; thread owns half2 column `lane`
    const unsigned* s32 =
        reinterpret_cast<const unsigned*>(tile) + g * 8 * 32 + lane;
    u64 win[8];
#pragma unroll
    for (int i = 0; i < 7; ++i) win[i] = h2f2(s32[i * 32]);
#pragma unroll
    for (int t = 0; t < 8; ++t) acc[t] = 0ull;
#pragma unroll
    for (int k = 0; k < KS; ++k) {
        win[(k + 7) & 7] = h2f2(s32[(k + 7) * 32]);
        const u64 w2 = pack2(Wc.w[k], Wc.w[k]);
#pragma unroll
        for (int t = 0; t < 8; ++t)
            fma2(acc[t], win[(k + t) & 7], w2);
    }
}

// band = prev - cur (packed, via fma with -1), store 8B, then prev <- cur
__device__ __forceinline__ void store_desc2(float* __restrict__ p,
                                            const u64 cur[8], u64 prev[8],
                                            u64 neg1) {
#pragma unroll
    for (int t = 0; t < 8; ++t) {
        *reinterpret_cast<u64*>(p + (size_t)t * W) = fma2v(cur[t], neg1, prev[t]);
        prev[t] = cur[t];
    }
}

__global__ __launch_bounds__(256) void vpass_kernel(const float* __restrict__ img,
                                                    float* __restrict__ out) {
    extern __shared__ __half smh[];
    const int tid  = threadIdx.x;
    const int lane = tid & 31;
    const int g    = tid >> 5;
    const int c0   = blockIdx.x * 64;
    const int R0   = blockIdx.y * 64;
    const int bc   = blockIdx.z;
    const int b    = bc / 3;
    const int ch   = bc - b * 3;
    const int rbase = R0 + g * 8;

    const __half* sbase = g_scratch + (size_t)bc * HW + c0;
    const unsigned smb = (unsigned)__cvta_generic_to_shared(smh);
    const u64 neg1 = pack2(-1.0f, -1.0f);

    // kick off the two largest tiles
    load_tile_async<117, BUFA>(smb, sbase + 5 * (size_t)NPIX, R0, tid);
    load_tile_async<59,  BUFB>(smb, sbase + 4 * (size_t)NPIX, R0, tid);

    u64 prev[8], cur[8];
    float* outp = out + ((size_t)b * 21 + ch) * HW + (size_t)rbase * W
                  + c0 + 2 * lane;

    // ---- sigma5 (A): band6 = G5
    cp_wait<1>(); __syncthreads();
    vconv2<117>(CW5, smh + BUFA, g, lane, cur);
#pragma unroll
    for (int t = 0; t < 8; ++t) {
        *reinterpret_cast<u64*>(outp + 6 * (size_t)(3 * HW) + (size_t)t * W) = cur[t];
        prev[t] = cur[t];
    }
    __syncthreads();
    load_tile_async<31, BUFA>(smb, sbase + 3 * (size_t)NPIX, R0, tid);

    // ---- sigma4 (B): band5 = G5 - G4
    cp_wait<1>(); __syncthreads();
    vconv2<59>(CW4, smh + BUFB, g, lane, cur);
    store_desc2(outp + 5 * (size_t)(3 * HW), cur, prev, neg1);
    __syncthreads();
    load_tile_async<17, BUFB>(smb, sbase + 2 * (size_t)NPIX, R0, tid);

    // ---- sigma3 (A): band4 = G4 - G3
    cp_wait<1>(); __syncthreads();
    vconv2<31>(CW3, smh + BUFA, g, lane, cur);
    store_desc2(outp + 4 * (size_t)(3 * HW), cur, prev, neg1);
    __syncthreads();
    load_tile_async<9, BUFA>(smb, sbase + 1 * (size_t)NPIX, R0, tid);

    // ---- sigma2 (B): band3 = G3 - G2
    cp_wait<1>(); __syncthreads();
    vconv2<17>(CW2, smh + BUFB, g, lane, cur);
    store_desc2(outp + 3 * (size_t)(3 * HW), cur, prev, neg1);
    __syncthreads();
    load_tile_async<7, BUFB>(smb, sbase + 0 * (size_t)NPIX, R0, tid);

    // ---- sigma1 (A): band2 = G2 - G1
    cp_wait<1>(); __syncthreads();
    vconv2<9>(CW1, smh + BUFA, g, lane, cur);
    store_desc2(outp + 2 * (size_t)(3 * HW), cur, prev, neg1);

    // ---- sigma0 (B): band1 = G1 - G0
    cp_wait<0>(); __syncthreads();
    vconv2<7>(CW0, smh + BUFB, g, lane, cur);
    store_desc2(outp + 1 * (size_t)(3 * HW), cur, prev, neg1);

    // band0 = G0 - img (prev holds G0); load img pairs directly as u64
    const float* imgp = img + (size_t)bc * HW + c0 + 2 * lane;
#pragma unroll
    for (int t = 0; t < 8; ++t) {
        u64 iv = *reinterpret_cast<const u64*>(imgp + (size_t)(rbase + t) * W);
        *reinterpret_cast<u64*>(outp + (size_t)t * W) = fma2v(iv, neg1, prev[t]);
    }
}

// ---------------------------------------------------------------------------
extern "C" void kernel_launch(void* const* d_in, const int* in_sizes, int n_in,
                              void* d_out, int out_size) {
    const float* img = (const float*)d_in[0];
    float* out = (float*)d_out;

    cudaFuncSetAttribute(vpass_kernel,
                         cudaFuncAttributeMaxDynamicSharedMemorySize,
                         VSMEM_BYTES);

    hpass_kernel<<<NROWS / 8, 256>>>(img);
    vpass_kernel<<<dim3(W / 64, H / 64, 8 * 3), 256, VSMEM_BYTES>>>(img, out);
}

// round 14
// speedup vs baseline: 1.1630x; 1.1630x over previous
#include <cuda_runtime.h>
#include <cuda_fp16.h>
#include <cstddef>

// ---------------------------------------------------------------------------
// Compile-time Gaussian weights (passed BY VALUE so they fold to FFMA-imm)
// ---------------------------------------------------------------------------
constexpr double cexp_pos(double x) {
    double term = 1.0, sum = 1.0;
    for (int i = 1; i < 200; ++i) {
        term *= x / (double)i;
        if (term < 1e-250) break;
        sum += term;
    }
    return sum;
}

template <int KS>
struct Wt { float w[KS]; };

template <int KS>
constexpr Wt<KS> make_w(double sigma) {
    Wt<KS> W{};
    double wd[KS]{};
    double s = 0.0;
    for (int i = 0; i < KS; ++i) {
        double d = (double)(i - KS / 2);
        double e = 1.0 / cexp_pos(d * d / (2.0 * sigma * sigma));
        wd[i] = e;
        s += e;
    }
    for (int i = 0; i < KS; ++i) W.w[i] = (float)(wd[i] / s);
    return W;
}

constexpr Wt<7>   CW0 = make_w<7>(0.6);
constexpr Wt<9>   CW1 = make_w<9>(1.2);
constexpr Wt<17>  CW2 = make_w<17>(2.4);
constexpr Wt<31>  CW3 = make_w<31>(4.8);
constexpr Wt<59>  CW4 = make_w<59>(9.6);
constexpr Wt<117> CW5 = make_w<117>(19.2);

constexpr int H = 512, W = 512;
constexpr int HW = H * W;
constexpr int NROWS = 8 * 3 * H;        // 12288
constexpr int NPIX = NROWS * W;         // 6291456
constexpr int PMAX = 58;

// fp16 h-blurred planes (75.5 MB)
__device__ __align__(16) __half g_scratch[6 * (size_t)NPIX];

// ---------------------------------------------------------------------------
// cp.async helpers
// ---------------------------------------------------------------------------
__device__ __forceinline__ void cp_async16(unsigned daddr, const void* gsrc) {
    asm volatile("cp.async.cg.shared.global [%0], [%1], 16;\n"
                 :: "r"(daddr), "l"(gsrc) : "memory");
}
__device__ __forceinline__ void cp_commit() {
    asm volatile("cp.async.commit_group;\n" ::: "memory");
}
template <int N>
__device__ __forceinline__ void cp_wait() {
    asm volatile("cp.async.wait_group %0;\n" :: "n"(N) : "memory");
}

// ---------------------------------------------------------------------------
// Kernel A: horizontal pass (round-12 proven version, fp16 output).
// CTA = 256 = 4 rows x 64 threads; 8 px/thread. Padded smem row
// (idx -> idx + idx/8): stride-8 lane access conflict-free (stride 9).
// ---------------------------------------------------------------------------
template <int KS>
__device__ __forceinline__ void hconv(const Wt<KS> Wc,
                                      const float* __restrict__ sr,
                                      int lane, __half* __restrict__ dst) {
    constexpr int P  = KS / 2;
    constexpr int S0 = PMAX - P;
    constexpr int Q  = S0 >> 3;
    constexpr int R  = S0 & 7;
    const int base = 9 * (lane + Q);

    float win[8], acc[8];
#pragma unroll
    for (int i = 0; i < 7; ++i)
        win[i] = sr[base + (R + i) + ((R + i) >> 3)];
#pragma unroll
    for (int t = 0; t < 8; ++t) acc[t] = 0.f;
#pragma unroll
    for (int k = 0; k < KS; ++k) {
        const int j = k + 7;
        win[j & 7] = sr[base + (R + j) + ((R + j) >> 3)];
#pragma unroll
        for (int t = 0; t < 8; ++t)
            acc[t] += Wc.w[k] * win[(k + t) & 7];
    }
    __half2 hh[4];
#pragma unroll
    for (int q = 0; q < 4; ++q)
        hh[q] = __floats2half2_rn(acc[2 * q], acc[2 * q + 1]);
    *reinterpret_cast<float4*>(dst + lane * 8) =
        *reinterpret_cast<const float4*>(hh);
}

__global__ __launch_bounds__(256, 4) void hpass_kernel(const float* __restrict__ img) {
    __shared__ float sr[4][712];
    const int grp = threadIdx.x >> 6;
    const int lt  = threadIdx.x & 63;
    const int row = blockIdx.x * 4 + grp;

    const float* rp = img + (size_t)row * W;
    for (int x = lt; x < W + 2 * PMAX; x += 64) {
        int gx = x - PMAX;
        gx = gx < 0 ? -gx : (gx > W - 1 ? 2 * W - 2 - gx : gx);
        sr[grp][x + (x >> 3)] = rp[gx];
    }
    __syncthreads();

    const float* s = sr[grp];
    __half* base = g_scratch + (size_t)row * W;
    hconv<7>(CW0, s, lt, base + 0 * (size_t)NPIX);
    hconv<9>(CW1, s, lt, base + 1 * (size_t)NPIX);
    hconv<17>(CW2, s, lt, base + 2 * (size_t)NPIX);
    hconv<31>(CW3, s, lt, base + 3 * (size_t)NPIX);
    hconv<59>(CW4, s, lt, base + 4 * (size_t)NPIX);
    hconv<117>(CW5, s, lt, base + 5 * (size_t)NPIX);
}

// ---------------------------------------------------------------------------
// Kernel B: vertical pass + DoG, double-buffered, DESCENDING sigma order,
// fp16 smem tiles, TALL tiles: 32 cols x 128 rows, 512 threads (16 warps x
// 8 rows). Halo factor (128+KS-1)/128 = 1.30x (vs 1.61x at 64 rows).
// Slot A = 244 rows (sigma 5,3,1), slot B = 186 rows (sigma 4,2,0).
// smem = 430 rows * 64 B = 27520 B -> 3 CTAs/SM (regfile-bound), 75% occ.
// ---------------------------------------------------------------------------
constexpr int VTHREADS = 512;
constexpr int TILER = 128;
constexpr int VSMEM_BYTES = (244 + 186) * 32 * 2;   // 27520
constexpr int BUFA = 0;                              // half-index, 244 rows
constexpr int BUFB = 244 * 32;                       // 186 rows

template <int KS, int OFF>
__device__ __forceinline__ void load_tile_async(unsigned smb,
                                                const __half* __restrict__ src,
                                                int R0, int tid) {
    constexpr int P  = KS / 2;
    constexpr int NR = TILER + KS - 1;
    const unsigned base = smb + (unsigned)OFF * 2u;
    const int c8 = (tid & 3) * 8;            // half offset of this thread's 16B
#pragma unroll 2
    for (int m = tid >> 2; m < NR; m += VTHREADS / 4) {
        int gr = R0 - P + m;
        gr = gr < 0 ? -gr : (gr > H - 1 ? 2 * H - 2 - gr : gr);
        cp_async16(base + (unsigned)(m * 32 + c8) * 2u,
                   src + (size_t)gr * W + c8);
    }
    cp_commit();
}

template <int KS>
__device__ __forceinline__ void vconv(const Wt<KS> Wc,
                                      const __half* __restrict__ smh,
                                      int g, int lane, float acc[8]) {
    const int base = g * 8 * 32 + lane;
    float win[8];
#pragma unroll
    for (int i = 0; i < 7; ++i) win[i] = __half2float(smh[base + i * 32]);
#pragma unroll
    for (int t = 0; t < 8; ++t) acc[t] = 0.f;
#pragma unroll
    for (int k = 0; k < KS; ++k) {
        win[(k + 7) & 7] = __half2float(smh[base + (k + 7) * 32]);
#pragma unroll
        for (int t = 0; t < 8; ++t)
            acc[t] += Wc.w[k] * win[(k + t) & 7];
    }
}

// band_{s+1} = prev - cur ; then prev <- cur
__device__ __forceinline__ void store_desc(float* __restrict__ p,
                                           const float cur[8], float prev[8]) {
#pragma unroll
    for (int t = 0; t < 8; ++t) {
        p[(size_t)t * W] = prev[t] - cur[t];
        prev[t] = cur[t];
    }
}

__global__ __launch_bounds__(VTHREADS) void vpass_kernel(const float* __restrict__ img,
                                                         float* __restrict__ out) {
    extern __shared__ __half smh[];
    const int tid  = threadIdx.x;
    const int lane = tid & 31;
    const int g    = tid >> 5;                 // 0..15
    const int c0   = blockIdx.x * 32;
    const int R0   = blockIdx.y * TILER;
    const int bc   = blockIdx.z;
    const int b    = bc / 3;
    const int ch   = bc - b * 3;
    const int rbase = R0 + g * 8;

    const __half* sbase = g_scratch + (size_t)bc * HW + c0;
    const unsigned smb = (unsigned)__cvta_generic_to_shared(smh);

    // kick off the two largest tiles
    load_tile_async<117, BUFA>(smb, sbase + 5 * (size_t)NPIX, R0, tid);
    load_tile_async<59,  BUFB>(smb, sbase + 4 * (size_t)NPIX, R0, tid);

    // img values for band0 (held in regs; LDG overlaps the cp.asyncs)
    const float* imgp = img + (size_t)bc * HW + c0 + lane;
    float imgv[8];
#pragma unroll
    for (int t = 0; t < 8; ++t) imgv[t] = imgp[(size_t)(rbase + t) * W];

    float prev[8], cur[8];
    float* outp = out + ((size_t)b * 21 + ch) * HW + (size_t)rbase * W + c0 + lane;

    // ---- sigma5 (A): band6 = G5
    cp_wait<1>(); __syncthreads();
    vconv<117>(CW5, smh + BUFA, g, lane, cur);
#pragma unroll
    for (int t = 0; t < 8; ++t) {
        outp[6 * (size_t)(3 * HW) + (size_t)t * W] = cur[t];
        prev[t] = cur[t];
    }
    __syncthreads();
    load_tile_async<31, BUFA>(smb, sbase + 3 * (size_t)NPIX, R0, tid);

    // ---- sigma4 (B): band5 = G5 - G4
    cp_wait<1>(); __syncthreads();
    vconv<59>(CW4, smh + BUFB, g, lane, cur);
    store_desc(outp + 5 * (size_t)(3 * HW), cur, prev);
    __syncthreads();
    load_tile_async<17, BUFB>(smb, sbase + 2 * (size_t)NPIX, R0, tid);

    // ---- sigma3 (A): band4 = G4 - G3
    cp_wait<1>(); __syncthreads();
    vconv<31>(CW3, smh + BUFA, g, lane, cur);
    store_desc(outp + 4 * (size_t)(3 * HW), cur, prev);
    __syncthreads();
    load_tile_async<9, BUFA>(smb, sbase + 1 * (size_t)NPIX, R0, tid);

    // ---- sigma2 (B): band3 = G3 - G2
    cp_wait<1>(); __syncthreads();
    vconv<17>(CW2, smh + BUFB, g, lane, cur);
    store_desc(outp + 3 * (size_t)(3 * HW), cur, prev);
    __syncthreads();
    load_tile_async<7, BUFB>(smb, sbase + 0 * (size_t)NPIX, R0, tid);

    // ---- sigma1 (A): band2 = G2 - G1
    cp_wait<1>(); __syncthreads();
    vconv<9>(CW1, smh + BUFA, g, lane, cur);
    store_desc(outp + 2 * (size_t)(3 * HW), cur, prev);

    // ---- sigma0 (B): band1 = G1 - G0
    cp_wait<0>(); __syncthreads();
    vconv<7>(CW0, smh + BUFB, g, lane, cur);
    store_desc(outp + 1 * (size_t)(3 * HW), cur, prev);

    // band0 = G0 - img (prev now holds G0)
#pragma unroll
    for (int t = 0; t < 8; ++t)
        outp[(size_t)t * W] = prev[t] - imgv[t];
}

// ---------------------------------------------------------------------------
extern "C" void kernel_launch(void* const* d_in, const int* in_sizes, int n_in,
                              void* d_out, int out_size) {
    const float* img = (const float*)d_in[0];
    float* out = (float*)d_out;

    cudaFuncSetAttribute(vpass_kernel,
                         cudaFuncAttributeMaxDynamicSharedMemorySize,
                         VSMEM_BYTES);

    hpass_kernel<<<NROWS / 4, 256>>>(img);
    vpass_kernel<<<dim3(W / 32, H / TILER, 8 * 3), VTHREADS, VSMEM_BYTES>>>(img, out);
}

// round 15
// speedup vs baseline: 1.4530x; 1.2493x over previous
#include <cuda_runtime.h>
#include <cuda_fp16.h>
#include <cstddef>

// ---------------------------------------------------------------------------
// Compile-time Gaussian weights (passed BY VALUE so they fold to FFMA-imm)
// ---------------------------------------------------------------------------
constexpr double cexp_pos(double x) {
    double term = 1.0, sum = 1.0;
    for (int i = 1; i < 200; ++i) {
        term *= x / (double)i;
        if (term < 1e-250) break;
        sum += term;
    }
    return sum;
}

template <int KS>
struct Wt { float w[KS]; };

template <int KS>
constexpr Wt<KS> make_w(double sigma) {
    Wt<KS> W{};
    double wd[KS]{};
    double s = 0.0;
    for (int i = 0; i < KS; ++i) {
        double d = (double)(i - KS / 2);
        double e = 1.0 / cexp_pos(d * d / (2.0 * sigma * sigma));
        wd[i] = e;
        s += e;
    }
    for (int i = 0; i < KS; ++i) W.w[i] = (float)(wd[i] / s);
    return W;
}

constexpr Wt<7>   CW0 = make_w<7>(0.6);
constexpr Wt<9>   CW1 = make_w<9>(1.2);
constexpr Wt<17>  CW2 = make_w<17>(2.4);
constexpr Wt<31>  CW3 = make_w<31>(4.8);
constexpr Wt<59>  CW4 = make_w<59>(9.6);
constexpr Wt<117> CW5 = make_w<117>(19.2);

constexpr int H = 512, W = 512;
constexpr int HW = H * W;
constexpr int NROWS = 8 * 3 * H;        // 12288
constexpr int NPIX = NROWS * W;         // 6291456
constexpr int PMAX = 58;

// fp16 h-blurred planes (75.5 MB)
__device__ __align__(16) __half g_scratch[6 * (size_t)NPIX];

// ---------------------------------------------------------------------------
// cp.async helpers
// ---------------------------------------------------------------------------
__device__ __forceinline__ void cp_async16(unsigned daddr, const void* gsrc) {
    asm volatile("cp.async.cg.shared.global [%0], [%1], 16;\n"
                 :: "r"(daddr), "l"(gsrc) : "memory");
}
__device__ __forceinline__ void cp_commit() {
    asm volatile("cp.async.commit_group;\n" ::: "memory");
}
template <int N>
__device__ __forceinline__ void cp_wait() {
    asm volatile("cp.async.wait_group %0;\n" :: "n"(N) : "memory");
}

// ---------------------------------------------------------------------------
// Kernel A: horizontal pass — WARP-PRIVATE segments, no CTA barrier.
// CTA = 256 thr = 8 warps. Warp w owns row (blk*4 + w/2), col half (w&1)*256:
// loads its own 372-float halo segment (reflect), __syncwarp(), then T=8 conv.
// Padded segment (idx -> idx + idx/8): window lane-stride 9, conflict-free.
// ---------------------------------------------------------------------------
constexpr int SEGW = 424;   // 372 valid -> padded max 417, round up

template <int KS>
__device__ __forceinline__ void hconv(const Wt<KS> Wc,
                                      const float* __restrict__ sr,
                                      int lane, __half* __restrict__ dst) {
    constexpr int P  = KS / 2;
    constexpr int S0 = PMAX - P;
    constexpr int Q  = S0 >> 3;
    constexpr int R  = S0 & 7;
    const int base = 9 * (lane + Q);

    float win[8], acc[8];
#pragma unroll
    for (int i = 0; i < 7; ++i)
        win[i] = sr[base + (R + i) + ((R + i) >> 3)];
#pragma unroll
    for (int t = 0; t < 8; ++t) acc[t] = 0.f;
#pragma unroll
    for (int k = 0; k < KS; ++k) {
        const int j = k + 7;
        win[j & 7] = sr[base + (R + j) + ((R + j) >> 3)];
#pragma unroll
        for (int t = 0; t < 8; ++t)
            acc[t] += Wc.w[k] * win[(k + t) & 7];
    }
    __half2 hh[4];
#pragma unroll
    for (int q = 0; q < 4; ++q)
        hh[q] = __floats2half2_rn(acc[2 * q], acc[2 * q + 1]);
    *reinterpret_cast<float4*>(dst + lane * 8) =
        *reinterpret_cast<const float4*>(hh);
}

__global__ __launch_bounds__(256) void hpass_kernel(const float* __restrict__ img) {
    __shared__ float sr[8][SEGW];
    const int wid  = threadIdx.x >> 5;        // 0..7
    const int lane = threadIdx.x & 31;
    const int row  = blockIdx.x * 4 + (wid >> 1);
    const int cbase = (wid & 1) * 256;        // col half

    const float* rp = img + (size_t)row * W;
    float* seg = sr[wid];
#pragma unroll
    for (int x = lane; x < 372; x += 32) {
        int gx = cbase + x - PMAX;
        gx = gx < 0 ? -gx : (gx > W - 1 ? 2 * W - 2 - gx : gx);
        seg[x + (x >> 3)] = rp[gx];
    }
    __syncwarp();

    __half* base = g_scratch + (size_t)row * W + cbase;
    hconv<7>(CW0, seg, lane, base + 0 * (size_t)NPIX);
    hconv<9>(CW1, seg, lane, base + 1 * (size_t)NPIX);
    hconv<17>(CW2, seg, lane, base + 2 * (size_t)NPIX);
    hconv<31>(CW3, seg, lane, base + 3 * (size_t)NPIX);
    hconv<59>(CW4, seg, lane, base + 4 * (size_t)NPIX);
    hconv<117>(CW5, seg, lane, base + 5 * (size_t)NPIX);
}

// ---------------------------------------------------------------------------
// Kernel B: vertical pass + DoG, double-buffered, DESCENDING sigma order,
// fp16 smem tiles (EXACT round-12 proven version: 70.4 us).
// Slot A (180 rows) holds sigma 5,3,1 tiles; slot B (122 rows) holds 4,2,0.
// smem = 302 rows * 64 B = 19328 B.
// ---------------------------------------------------------------------------
constexpr int VSMEM_BYTES = 302 * 32 * 2;    // 19328
constexpr int BUFA = 0;                       // half-index
constexpr int BUFB = 180 * 32;

template <int KS, int OFF>
__device__ __forceinline__ void load_tile_async(unsigned smb,
                                                const __half* __restrict__ src,
                                                int R0, int tid) {
    constexpr int P  = KS / 2;
    constexpr int NR = 64 + KS - 1;
    const unsigned base = smb + (unsigned)OFF * 2u;
    const int c8 = (tid & 3) * 8;            // half offset of this thread's 16B
#pragma unroll 2
    for (int m = tid >> 2; m < NR; m += 64) {
        int gr = R0 - P + m;
        gr = gr < 0 ? -gr : (gr > H - 1 ? 2 * H - 2 - gr : gr);
        cp_async16(base + (unsigned)(m * 32 + c8) * 2u,
                   src + (size_t)gr * W + c8);
    }
    cp_commit();
}

template <int KS>
__device__ __forceinline__ void vconv(const Wt<KS> Wc,
                                      const __half* __restrict__ smh,
                                      int g, int lane, float acc[8]) {
    const int base = g * 8 * 32 + lane;
    float win[8];
#pragma unroll
    for (int i = 0; i < 7; ++i) win[i] = __half2float(smh[base + i * 32]);
#pragma unroll
    for (int t = 0; t < 8; ++t) acc[t] = 0.f;
#pragma unroll
    for (int k = 0; k < KS; ++k) {
        win[(k + 7) & 7] = __half2float(smh[base + (k + 7) * 32]);
#pragma unroll
        for (int t = 0; t < 8; ++t)
            acc[t] += Wc.w[k] * win[(k + t) & 7];
    }
}

// band_{s+1} = prev - cur ; then prev <- cur
__device__ __forceinline__ void store_desc(float* __restrict__ p,
                                           const float cur[8], float prev[8]) {
#pragma unroll
    for (int t = 0; t < 8; ++t) {
        p[(size_t)t * W] = prev[t] - cur[t];
        prev[t] = cur[t];
    }
}

__global__ __launch_bounds__(256) void vpass_kernel(const float* __restrict__ img,
                                                    float* __restrict__ out) {
    extern __shared__ __half smh[];
    const int tid  = threadIdx.x;
    const int lane = tid & 31;
    const int g    = tid >> 5;
    const int c0   = blockIdx.x * 32;
    const int R0   = blockIdx.y * 64;
    const int bc   = blockIdx.z;
    const int b    = bc / 3;
    const int ch   = bc - b * 3;
    const int rbase = R0 + g * 8;

    const __half* sbase = g_scratch + (size_t)bc * HW + c0;
    const unsigned smb = (unsigned)__cvta_generic_to_shared(smh);

    // kick off the two largest tiles
    load_tile_async<117, BUFA>(smb, sbase + 5 * (size_t)NPIX, R0, tid);
    load_tile_async<59,  BUFB>(smb, sbase + 4 * (size_t)NPIX, R0, tid);

    // img values for band0 (held in regs; LDG overlaps the cp.asyncs)
    const float* imgp = img + (size_t)bc * HW + c0 + lane;
    float imgv[8];
#pragma unroll
    for (int t = 0; t < 8; ++t) imgv[t] = imgp[(size_t)(rbase + t) * W];

    float prev[8], cur[8];
    float* outp = out + ((size_t)b * 21 + ch) * HW + (size_t)rbase * W + c0 + lane;

    // ---- sigma5 (A): band6 = G5
    cp_wait<1>(); __syncthreads();
    vconv<117>(CW5, smh + BUFA, g, lane, cur);
#pragma unroll
    for (int t = 0; t < 8; ++t) {
        outp[6 * (size_t)(3 * HW) + (size_t)t * W] = cur[t];
        prev[t] = cur[t];
    }
    __syncthreads();
    load_tile_async<31, BUFA>(smb, sbase + 3 * (size_t)NPIX, R0, tid);

    // ---- sigma4 (B): band5 = G5 - G4
    cp_wait<1>(); __syncthreads();
    vconv<59>(CW4, smh + BUFB, g, lane, cur);
    store_desc(outp + 5 * (size_t)(3 * HW), cur, prev);
    __syncthreads();
    load_tile_async<17, BUFB>(smb, sbase + 2 * (size_t)NPIX, R0, tid);

    // ---- sigma3 (A): band4 = G4 - G3
    cp_wait<1>(); __syncthreads();
    vconv<31>(CW3, smh + BUFA, g, lane, cur);
    store_desc(outp + 4 * (size_t)(3 * HW), cur, prev);
    __syncthreads();
    load_tile_async<9, BUFA>(smb, sbase + 1 * (size_t)NPIX, R0, tid);

    // ---- sigma2 (B): band3 = G3 - G2
    cp_wait<1>(); __syncthreads();
    vconv<17>(CW2, smh + BUFB, g, lane, cur);
    store_desc(outp + 3 * (size_t)(3 * HW), cur, prev);
    __syncthreads();
    load_tile_async<7, BUFB>(smb, sbase + 0 * (size_t)NPIX, R0, tid);

    // ---- sigma1 (A): band2 = G2 - G1
    cp_wait<1>(); __syncthreads();
    vconv<9>(CW1, smh + BUFA, g, lane, cur);
    store_desc(outp + 2 * (size_t)(3 * HW), cur, prev);

    // ---- sigma0 (B): band1 = G1 - G0
    cp_wait<0>(); __syncthreads();
    vconv<7>(CW0, smh + BUFB, g, lane, cur);
    store_desc(outp + 1 * (size_t)(3 * HW), cur, prev);

    // band0 = G0 - img (prev now holds G0)
#pragma unroll
    for (int t = 0; t < 8; ++t)
        outp[(size_t)t * W] = prev[t] - imgv[t];
}

// ---------------------------------------------------------------------------
extern "C" void kernel_launch(void* const* d_in, const int* in_sizes, int n_in,
                              void* d_out, int out_size) {
    const float* img = (const float*)d_in[0];
    float* out = (float*)d_out;

    cudaFuncSetAttribute(vpass_kernel,
                         cudaFuncAttributeMaxDynamicSharedMemorySize,
                         VSMEM_BYTES);

    hpass_kernel<<<NROWS / 4, 256>>>(img);
    vpass_kernel<<<dim3(W / 32, H / 64, 8 * 3), 256, VSMEM_BYTES>>>(img, out);
}